// round 13
// baseline (speedup 1.0000x reference)
#include <cuda_runtime.h>
#include <cuda_fp16.h>
#include <cstdint>
#include <math.h>

// Scratch: R = masked q_rm.k/8 stored fp16 (zeros above diagonal; unwritten
// strictly-upper tiles rely on zero-init), P = 0.54*attn + 0.324*attn_rm (f32).
__device__ __half g_R[67108864];
__device__ float  g_P[67108864];

__device__ __forceinline__ void mma16816(float* d,
                                         uint32_t a0, uint32_t a1,
                                         uint32_t a2, uint32_t a3,
                                         uint32_t b0, uint32_t b1) {
    asm volatile(
        "mma.sync.aligned.m16n8k16.row.col.f32.f16.f16.f32 "
        "{%0,%1,%2,%3},{%4,%5,%6,%7},{%8,%9},{%0,%1,%2,%3};\n"
        : "+f"(d[0]), "+f"(d[1]), "+f"(d[2]), "+f"(d[3])
        : "r"(a0), "r"(a1), "r"(a2), "r"(a3), "r"(b0), "r"(b1));
}

// ---------------------------------------------------------------------------
// K1: dual GEMM on tensor cores (P: fp16 split-2, 3 MMAs; R: fp16, 1 MMA).
// ---------------------------------------------------------------------------
__global__ void __launch_bounds__(256) k1_tc(const float* __restrict__ q,
                                             const float* __restrict__ qrm,
                                             const float* __restrict__ kk) {
    const int bx = blockIdx.x, by = blockIdx.y, n = blockIdx.z;
    if (bx > 2 * by + 1) return;
    const int i0 = by << 7, j0 = bx << 6;
    extern __shared__ __half sh[];
    __half* sCh = sh;
    __half* sCl = sh + 9216;
    __half* sRh = sh + 2 * 9216;
    __half* sBh = sh + 3 * 9216;
    __half* sBl = sh + 3 * 9216 + 4608;
    const int tid = threadIdx.x;
    const float* qb = q   + (n << 16) + (i0 << 6);
    const float* rb = qrm + (n << 16) + (i0 << 6);
    const float* kb = kk  + (n << 16) + (j0 << 6);
    for (int p = tid; p < 4096; p += 256) {
        int row = p >> 5, dp = (p & 31) << 1;
        float2 qv = *(const float2*)&qb[(row << 6) + dp];
        float2 rv = *(const float2*)&rb[(row << 6) + dp];
        float c0 = (0.54f * qv.x + 0.324f * rv.x) * 0.125f;
        float c1 = (0.54f * qv.y + 0.324f * rv.y) * 0.125f;
        __half ch0 = __float2half_rn(c0), ch1 = __float2half_rn(c1);
        float l0 = c0 - __half2float(ch0), l1 = c1 - __half2float(ch1);
        int o = row * 72 + dp;
        *(__half2*)&sCh[o] = __halves2half2(ch0, ch1);
        *(__half2*)&sCl[o] = __floats2half2_rn(l0, l1);
        *(__half2*)&sRh[o] = __floats2half2_rn(rv.x * 0.125f, rv.y * 0.125f);
    }
    for (int p = tid; p < 2048; p += 256) {
        int row = p >> 5, dp = (p & 31) << 1;
        float2 kv = *(const float2*)&kb[(row << 6) + dp];
        __half h0 = __float2half_rn(kv.x), h1 = __float2half_rn(kv.y);
        float l0 = kv.x - __half2float(h0), l1 = kv.y - __half2float(h1);
        int o = row * 72 + dp;
        *(__half2*)&sBh[o] = __halves2half2(h0, h1);
        *(__half2*)&sBl[o] = __floats2half2_rn(l0, l1);
    }
    __syncthreads();

    const int w = tid >> 5, lane = tid & 31;
    const int g = lane >> 2, tg = lane & 3;
    const int rowA = 16 * w + g;
    float pA[8][4] = {}, rA[8][4] = {};

#pragma unroll
    for (int kc = 0; kc < 4; kc++) {
        const int kb0 = 16 * kc + 2 * tg;
        const int oa0 = rowA * 72 + kb0;
        const int oa1 = (rowA + 8) * 72 + kb0;
        uint32_t ch0 = *(const uint32_t*)&sCh[oa0];
        uint32_t ch1 = *(const uint32_t*)&sCh[oa1];
        uint32_t ch2 = *(const uint32_t*)&sCh[oa0 + 8];
        uint32_t ch3 = *(const uint32_t*)&sCh[oa1 + 8];
        uint32_t cl0 = *(const uint32_t*)&sCl[oa0];
        uint32_t cl1 = *(const uint32_t*)&sCl[oa1];
        uint32_t cl2 = *(const uint32_t*)&sCl[oa0 + 8];
        uint32_t cl3 = *(const uint32_t*)&sCl[oa1 + 8];
        uint32_t rh0 = *(const uint32_t*)&sRh[oa0];
        uint32_t rh1 = *(const uint32_t*)&sRh[oa1];
        uint32_t rh2 = *(const uint32_t*)&sRh[oa0 + 8];
        uint32_t rh3 = *(const uint32_t*)&sRh[oa1 + 8];
#pragma unroll
        for (int nt = 0; nt < 8; nt++) {
            const int ob = (8 * nt + g) * 72 + kb0;
            uint32_t bh0 = *(const uint32_t*)&sBh[ob];
            uint32_t bh1 = *(const uint32_t*)&sBh[ob + 8];
            uint32_t bl0 = *(const uint32_t*)&sBl[ob];
            uint32_t bl1 = *(const uint32_t*)&sBl[ob + 8];
            mma16816(pA[nt], ch0, ch1, ch2, ch3, bh0, bh1);
            mma16816(pA[nt], ch0, ch1, ch2, ch3, bl0, bl1);
            mma16816(pA[nt], cl0, cl1, cl2, cl3, bh0, bh1);
            mma16816(rA[nt], rh0, rh1, rh2, rh3, bh0, bh1);
        }
    }

    const int r0g = i0 + rowA;
    const int r1g = r0g + 8;
#pragma unroll
    for (int nt = 0; nt < 8; nt++) {
        const int c0 = j0 + 8 * nt + 2 * tg;
        const int off0 = (n << 20) + (r0g << 10) + c0;
        const int off1 = (n << 20) + (r1g << 10) + c0;
        *(float2*)&g_P[off0] = make_float2(pA[nt][0], pA[nt][1]);
        *(float2*)&g_P[off1] = make_float2(pA[nt][2], pA[nt][3]);
        float m00 = (c0     <= r0g) ? rA[nt][0] : 0.f;
        float m01 = (c0 + 1 <= r0g) ? rA[nt][1] : 0.f;
        float m10 = (c0     <= r1g) ? rA[nt][2] : 0.f;
        float m11 = (c0 + 1 <= r1g) ? rA[nt][3] : 0.f;
        *(__half2*)&g_R[off0] = __floats2half2_rn(m00, m01);
        *(__half2*)&g_R[off1] = __floats2half2_rn(m10, m11);
    }
}

// ---------------------------------------------------------------------------
// K2: 3x3 conv on R (fp16), relu, shift, boundary fix, mix into P.
// ---------------------------------------------------------------------------
__global__ void __launch_bounds__(256) k2_conv(const float* __restrict__ pre,
                                               const float* __restrict__ cw) {
    const int bx = blockIdx.x, by = blockIdx.y, b = blockIdx.z;
    if (bx > by) return;
    const int i0 = by << 5, j0 = bx << 5;
    __shared__ float xs[8 * 34 * 34];
    __shared__ float ws[576];
    const int tid = threadIdx.x;
    for (int w = tid; w < 576; w += 256) ws[w] = cw[w];
    for (int idx = tid; idx < 9248; idx += 256) {
        int c = idx / 1156;
        int rem = idx - c * 1156;
        int li = rem / 34;
        int lj = rem - li * 34;
        int gi = i0 - 2 + li, gj = j0 - 2 + lj;
        float vv = 0.f;
        if (gi >= 0 && gj >= 0)
            vv = __half2float(g_R[((b * 8 + c) << 20) + (gi << 10) + gj]);
        xs[idx] = vv;
    }
    __syncthreads();
    const int ir = tid >> 3;
    const int jb = (tid & 7) << 2;
    float acc[8][4];
#pragma unroll
    for (int o = 0; o < 8; o++)
#pragma unroll
        for (int t = 0; t < 4; t++) acc[o][t] = 0.f;
#pragma unroll 1
    for (int c = 0; c < 8; c++) {
#pragma unroll
        for (int kh = 0; kh < 3; kh++) {
            const float* xr = &xs[c * 1156 + (ir + kh) * 34 + jb];
            float x0 = xr[0], x1 = xr[1], x2 = xr[2],
                  x3 = xr[3], x4 = xr[4], x5 = xr[5];
#pragma unroll
            for (int o = 0; o < 8; o++) {
                const float* wp = &ws[o * 72 + c * 9 + kh * 3];
                float w0 = wp[0], w1 = wp[1], w2 = wp[2];
                acc[o][0] += x0 * w0 + x1 * w1 + x2 * w2;
                acc[o][1] += x1 * w0 + x2 * w1 + x3 * w2;
                acc[o][2] += x2 * w0 + x3 * w1 + x4 * w2;
                acc[o][3] += x3 * w0 + x4 * w1 + x5 * w2;
            }
        }
    }
    const int i = i0 + ir;
#pragma unroll
    for (int o = 0; o < 8; o++) {
        const int n = b * 8 + o;
        const int base = (n << 20) + (i << 10) + j0 + jb;
        float4 Pv = *(const float4*)&g_P[base];
        float4 Av = *(const float4*)&pre[base];
        float pv[4] = {Pv.x, Pv.y, Pv.z, Pv.w};
        float av[4] = {Av.x, Av.y, Av.z, Av.w};
        float ov[4];
#pragma unroll
        for (int t = 0; t < 4; t++) {
            const int j = j0 + jb + t;
            float shv;
            if (i == 0)       shv = __half2float(g_R[(n << 20) + j]);
            else if (j == 0)  shv = __half2float(g_R[(n << 20) + (i << 10)]);
            else              shv = fmaxf(acc[o][t], 0.f);
            ov[t] = pv[t] + 0.1f * av[t] + 0.036f * shv;
        }
        *(float4*)&g_P[base] = make_float4(ov[0], ov[1], ov[2], ov[3]);
    }
}

// ---------------------------------------------------------------------------
// K3: causal softmax, one block per row; one float4 per thread.
// ---------------------------------------------------------------------------
__global__ void __launch_bounds__(256) k3_softmax(float* __restrict__ attn_out) {
    const int i = blockIdx.x, n = blockIdx.y;
    const int m = i + 1;
    __shared__ float red[8];
    const int tid = threadIdx.x;
    const int base = (n << 20) + (i << 10);
    const int jb = tid << 2;
    float v0 = -1e30f, v1 = -1e30f, v2 = -1e30f, v3 = -1e30f;
    if (jb < m) {
        float4 pv = *(const float4*)&g_P[base + jb];
        v0 = pv.x;
        v1 = (jb + 1 < m) ? pv.y : -1e30f;
        v2 = (jb + 2 < m) ? pv.z : -1e30f;
        v3 = (jb + 3 < m) ? pv.w : -1e30f;
    }
    float lmax = fmaxf(fmaxf(v0, v1), fmaxf(v2, v3));
#pragma unroll
    for (int o = 16; o > 0; o >>= 1)
        lmax = fmaxf(lmax, __shfl_xor_sync(0xffffffffu, lmax, o));
    if ((tid & 31) == 0) red[tid >> 5] = lmax;
    __syncthreads();
    float mx = red[0];
#pragma unroll
    for (int w = 1; w < 8; w++) mx = fmaxf(mx, red[w]);
    float e0 = (jb     < m) ? expf(v0 - mx) : 0.f;
    float e1 = (jb + 1 < m) ? expf(v1 - mx) : 0.f;
    float e2 = (jb + 2 < m) ? expf(v2 - mx) : 0.f;
    float e3 = (jb + 3 < m) ? expf(v3 - mx) : 0.f;
    float lsum = (e0 + e1) + (e2 + e3);
#pragma unroll
    for (int o = 16; o > 0; o >>= 1)
        lsum += __shfl_xor_sync(0xffffffffu, lsum, o);
    __syncthreads();
    if ((tid & 31) == 0) red[tid >> 5] = lsum;
    __syncthreads();
    float tot = 0.f;
#pragma unroll
    for (int w = 0; w < 8; w++) tot += red[w];
    const float inv = 1.f / tot;
    *(float4*)&attn_out[base + jb] =
        make_float4(e0 * inv, e1 * inv, e2 * inv, e3 * inv);
}

// ---------------------------------------------------------------------------
// K4: out = attn @ v. 64x64 tile, 4x4 micro, 256 threads. Both A and V tiles
// double-buffered: next tile's values prefetched into registers before the
// current tile's compute (LDG latency hidden), stored to the alternate smem
// buffers after compute; ONE barrier per tile.
// ---------------------------------------------------------------------------
__global__ void __launch_bounds__(256) k4_pv(const float* __restrict__ attn,
                                             const float* __restrict__ v,
                                             float* __restrict__ out) {
    const int it = blockIdx.x, n = blockIdx.y;
    const int i0 = it << 6;
    extern __shared__ float sm4[];
    // Buffers: A0, V0, A1, V1 — each 64x68.
    float* sA[2] = {sm4, sm4 + 2 * 64 * 68};
    float* sV[2] = {sm4 + 64 * 68, sm4 + 3 * 64 * 68};
    const int tid = threadIdx.y * 16 + threadIdx.x;
    const int ty4 = threadIdx.y * 4, tx4 = threadIdx.x * 4;
    // Fill tile 0 (both A transposed [j][i] and V [j][d]).
    for (int idx = tid; idx < 4096; idx += 256) {
        int rr = idx >> 6, cc = idx & 63;
        sA[0][cc * 68 + rr] = attn[(n << 20) + ((i0 + rr) << 10) + cc];
        sV[0][rr * 68 + cc] = v[(n << 16) + (rr << 6) + cc];
    }
    __syncthreads();
    float acc[4][4] = {};
    int cur = 0;
    for (int jt = 0; jt <= it; jt++) {
        const bool pref = (jt < it);
        float pa[16], pv[16];
        if (pref) {
            const int j0n = (jt + 1) << 6;
#pragma unroll
            for (int t = 0; t < 16; t++) {
                int idx = tid + t * 256;
                int rr = idx >> 6, cc = idx & 63;
                pa[t] = attn[(n << 20) + ((i0 + rr) << 10) + j0n + cc];
                pv[t] = v[(n << 16) + ((j0n + rr) << 6) + cc];
            }
        }
        const float* A = sA[cur];
        const float* V = sV[cur];
#pragma unroll 8
        for (int lj = 0; lj < 64; lj++) {
            float4 a = *(const float4*)&A[lj * 68 + ty4];
            float4 b = *(const float4*)&V[lj * 68 + tx4];
            float av[4] = {a.x, a.y, a.z, a.w};
            float bv[4] = {b.x, b.y, b.z, b.w};
#pragma unroll
            for (int r = 0; r < 4; r++)
#pragma unroll
                for (int c = 0; c < 4; c++)
                    acc[r][c] += av[r] * bv[c];
        }
        if (pref) {
            float* An = sA[cur ^ 1];
            float* Vn = sV[cur ^ 1];
#pragma unroll
            for (int t = 0; t < 16; t++) {
                int idx = tid + t * 256;
                int rr = idx >> 6, cc = idx & 63;
                An[cc * 68 + rr] = pa[t];
                Vn[rr * 68 + cc] = pv[t];
            }
            __syncthreads();
            cur ^= 1;
        }
    }
#pragma unroll
    for (int r = 0; r < 4; r++) {
        const int gi = i0 + ty4 + r;
        *(float4*)&out[(n << 16) + (gi << 6) + tx4] =
            make_float4(acc[r][0], acc[r][1], acc[r][2], acc[r][3]);
    }
}

extern "C" void kernel_launch(void* const* d_in, const int* in_sizes, int n_in,
                              void* d_out, int out_size) {
    const float* q   = (const float*)d_in[0];
    const float* k   = (const float*)d_in[1];
    const float* v   = (const float*)d_in[2];
    const float* qrm = (const float*)d_in[3];
    const float* pre = (const float*)d_in[4];
    const float* cw  = (const float*)d_in[5];
    // d_in[6] = mask (recomputed analytically), d_in[7] = fg (always 1)

    float* out      = (float*)d_out;            // (64,1024,64)
    float* attn_out = out + 64 * 1024 * 64;     // (64,1024,1024)

    const int k1_smem = (3 * 9216 + 2 * 4608) * sizeof(__half);  // 73728 B
    const int k4_smem = 4 * 64 * 68 * sizeof(float);             // 69632 B
    cudaFuncSetAttribute(k1_tc, cudaFuncAttributeMaxDynamicSharedMemorySize,
                         k1_smem);
    cudaFuncSetAttribute(k4_pv, cudaFuncAttributeMaxDynamicSharedMemorySize,
                         k4_smem);

    k1_tc<<<dim3(16, 8, 64), 256, k1_smem>>>(q, qrm, k);
    k2_conv<<<dim3(32, 32, 8), 256>>>(pre, cw);
    k3_softmax<<<dim3(1024, 64), 256>>>(attn_out);
    k4_pv<<<dim3(16, 64), dim3(16, 16), k4_smem>>>(attn_out, v, out);
}

// round 14
// speedup vs baseline: 1.0403x; 1.0403x over previous
#include <cuda_runtime.h>
#include <cuda_fp16.h>
#include <cstdint>
#include <math.h>

// Scratch: R = masked q_rm.k/8 stored fp16 (zeros above diagonal; unwritten
// strictly-upper tiles rely on zero-init), P = 0.54*attn + 0.324*attn_rm (f32).
__device__ __half g_R[67108864];
__device__ float  g_P[67108864];

__device__ __forceinline__ void mma16816(float* d,
                                         uint32_t a0, uint32_t a1,
                                         uint32_t a2, uint32_t a3,
                                         uint32_t b0, uint32_t b1) {
    asm volatile(
        "mma.sync.aligned.m16n8k16.row.col.f32.f16.f16.f32 "
        "{%0,%1,%2,%3},{%4,%5,%6,%7},{%8,%9},{%0,%1,%2,%3};\n"
        : "+f"(d[0]), "+f"(d[1]), "+f"(d[2]), "+f"(d[3])
        : "r"(a0), "r"(a1), "r"(a2), "r"(a3), "r"(b0), "r"(b1));
}

// ---------------------------------------------------------------------------
// K1: dual GEMM on tensor cores (P: fp16 split-2, 3 MMAs; R: fp16, 1 MMA).
// C tile 128(i) x 64(j), K=64. Tiles kept iff bx <= 2*by+1.
// ---------------------------------------------------------------------------
__global__ void __launch_bounds__(256) k1_tc(const float* __restrict__ q,
                                             const float* __restrict__ qrm,
                                             const float* __restrict__ kk) {
    const int bx = blockIdx.x, by = blockIdx.y, n = blockIdx.z;
    if (bx > 2 * by + 1) return;
    const int i0 = by << 7, j0 = bx << 6;
    extern __shared__ __half sh[];
    __half* sCh = sh;
    __half* sCl = sh + 9216;
    __half* sRh = sh + 2 * 9216;
    __half* sBh = sh + 3 * 9216;
    __half* sBl = sh + 3 * 9216 + 4608;
    const int tid = threadIdx.x;
    const float* qb = q   + (n << 16) + (i0 << 6);
    const float* rb = qrm + (n << 16) + (i0 << 6);
    const float* kb = kk  + (n << 16) + (j0 << 6);
    for (int p = tid; p < 4096; p += 256) {
        int row = p >> 5, dp = (p & 31) << 1;
        float2 qv = *(const float2*)&qb[(row << 6) + dp];
        float2 rv = *(const float2*)&rb[(row << 6) + dp];
        float c0 = (0.54f * qv.x + 0.324f * rv.x) * 0.125f;
        float c1 = (0.54f * qv.y + 0.324f * rv.y) * 0.125f;
        __half ch0 = __float2half_rn(c0), ch1 = __float2half_rn(c1);
        float l0 = c0 - __half2float(ch0), l1 = c1 - __half2float(ch1);
        int o = row * 72 + dp;
        *(__half2*)&sCh[o] = __halves2half2(ch0, ch1);
        *(__half2*)&sCl[o] = __floats2half2_rn(l0, l1);
        *(__half2*)&sRh[o] = __floats2half2_rn(rv.x * 0.125f, rv.y * 0.125f);
    }
    for (int p = tid; p < 2048; p += 256) {
        int row = p >> 5, dp = (p & 31) << 1;
        float2 kv = *(const float2*)&kb[(row << 6) + dp];
        __half h0 = __float2half_rn(kv.x), h1 = __float2half_rn(kv.y);
        float l0 = kv.x - __half2float(h0), l1 = kv.y - __half2float(h1);
        int o = row * 72 + dp;
        *(__half2*)&sBh[o] = __halves2half2(h0, h1);
        *(__half2*)&sBl[o] = __floats2half2_rn(l0, l1);
    }
    __syncthreads();

    const int w = tid >> 5, lane = tid & 31;
    const int g = lane >> 2, tg = lane & 3;
    const int rowA = 16 * w + g;
    float pA[8][4] = {}, rA[8][4] = {};

#pragma unroll
    for (int kc = 0; kc < 4; kc++) {
        const int kb0 = 16 * kc + 2 * tg;
        const int oa0 = rowA * 72 + kb0;
        const int oa1 = (rowA + 8) * 72 + kb0;
        uint32_t ch0 = *(const uint32_t*)&sCh[oa0];
        uint32_t ch1 = *(const uint32_t*)&sCh[oa1];
        uint32_t ch2 = *(const uint32_t*)&sCh[oa0 + 8];
        uint32_t ch3 = *(const uint32_t*)&sCh[oa1 + 8];
        uint32_t cl0 = *(const uint32_t*)&sCl[oa0];
        uint32_t cl1 = *(const uint32_t*)&sCl[oa1];
        uint32_t cl2 = *(const uint32_t*)&sCl[oa0 + 8];
        uint32_t cl3 = *(const uint32_t*)&sCl[oa1 + 8];
        uint32_t rh0 = *(const uint32_t*)&sRh[oa0];
        uint32_t rh1 = *(const uint32_t*)&sRh[oa1];
        uint32_t rh2 = *(const uint32_t*)&sRh[oa0 + 8];
        uint32_t rh3 = *(const uint32_t*)&sRh[oa1 + 8];
#pragma unroll
        for (int nt = 0; nt < 8; nt++) {
            const int ob = (8 * nt + g) * 72 + kb0;
            uint32_t bh0 = *(const uint32_t*)&sBh[ob];
            uint32_t bh1 = *(const uint32_t*)&sBh[ob + 8];
            uint32_t bl0 = *(const uint32_t*)&sBl[ob];
            uint32_t bl1 = *(const uint32_t*)&sBl[ob + 8];
            mma16816(pA[nt], ch0, ch1, ch2, ch3, bh0, bh1);
            mma16816(pA[nt], ch0, ch1, ch2, ch3, bl0, bl1);
            mma16816(pA[nt], cl0, cl1, cl2, cl3, bh0, bh1);
            mma16816(rA[nt], rh0, rh1, rh2, rh3, bh0, bh1);
        }
    }

    const int r0g = i0 + rowA;
    const int r1g = r0g + 8;
#pragma unroll
    for (int nt = 0; nt < 8; nt++) {
        const int c0 = j0 + 8 * nt + 2 * tg;
        const int off0 = (n << 20) + (r0g << 10) + c0;
        const int off1 = (n << 20) + (r1g << 10) + c0;
        *(float2*)&g_P[off0] = make_float2(pA[nt][0], pA[nt][1]);
        *(float2*)&g_P[off1] = make_float2(pA[nt][2], pA[nt][3]);
        float m00 = (c0     <= r0g) ? rA[nt][0] : 0.f;
        float m01 = (c0 + 1 <= r0g) ? rA[nt][1] : 0.f;
        float m10 = (c0     <= r1g) ? rA[nt][2] : 0.f;
        float m11 = (c0 + 1 <= r1g) ? rA[nt][3] : 0.f;
        *(__half2*)&g_R[off0] = __floats2half2_rn(m00, m01);
        *(__half2*)&g_R[off1] = __floats2half2_rn(m10, m11);
    }
}

// ---------------------------------------------------------------------------
// K2: 3x3 conv on R (fp16), relu, shift, boundary fix, mix into P.
// ---------------------------------------------------------------------------
__global__ void __launch_bounds__(256) k2_conv(const float* __restrict__ pre,
                                               const float* __restrict__ cw) {
    const int bx = blockIdx.x, by = blockIdx.y, b = blockIdx.z;
    if (bx > by) return;
    const int i0 = by << 5, j0 = bx << 5;
    __shared__ float xs[8 * 34 * 34];
    __shared__ float ws[576];
    const int tid = threadIdx.x;
    for (int w = tid; w < 576; w += 256) ws[w] = cw[w];
    for (int idx = tid; idx < 9248; idx += 256) {
        int c = idx / 1156;
        int rem = idx - c * 1156;
        int li = rem / 34;
        int lj = rem - li * 34;
        int gi = i0 - 2 + li, gj = j0 - 2 + lj;
        float vv = 0.f;
        if (gi >= 0 && gj >= 0)
            vv = __half2float(g_R[((b * 8 + c) << 20) + (gi << 10) + gj]);
        xs[idx] = vv;
    }
    __syncthreads();
    const int ir = tid >> 3;
    const int jb = (tid & 7) << 2;
    float acc[8][4];
#pragma unroll
    for (int o = 0; o < 8; o++)
#pragma unroll
        for (int t = 0; t < 4; t++) acc[o][t] = 0.f;
#pragma unroll 1
    for (int c = 0; c < 8; c++) {
#pragma unroll
        for (int kh = 0; kh < 3; kh++) {
            const float* xr = &xs[c * 1156 + (ir + kh) * 34 + jb];
            float x0 = xr[0], x1 = xr[1], x2 = xr[2],
                  x3 = xr[3], x4 = xr[4], x5 = xr[5];
#pragma unroll
            for (int o = 0; o < 8; o++) {
                const float* wp = &ws[o * 72 + c * 9 + kh * 3];
                float w0 = wp[0], w1 = wp[1], w2 = wp[2];
                acc[o][0] += x0 * w0 + x1 * w1 + x2 * w2;
                acc[o][1] += x1 * w0 + x2 * w1 + x3 * w2;
                acc[o][2] += x2 * w0 + x3 * w1 + x4 * w2;
                acc[o][3] += x3 * w0 + x4 * w1 + x5 * w2;
            }
        }
    }
    const int i = i0 + ir;
#pragma unroll
    for (int o = 0; o < 8; o++) {
        const int n = b * 8 + o;
        const int base = (n << 20) + (i << 10) + j0 + jb;
        float4 Pv = *(const float4*)&g_P[base];
        float4 Av = *(const float4*)&pre[base];
        float pv[4] = {Pv.x, Pv.y, Pv.z, Pv.w};
        float av[4] = {Av.x, Av.y, Av.z, Av.w};
        float ov[4];
#pragma unroll
        for (int t = 0; t < 4; t++) {
            const int j = j0 + jb + t;
            float shv;
            if (i == 0)       shv = __half2float(g_R[(n << 20) + j]);
            else if (j == 0)  shv = __half2float(g_R[(n << 20) + (i << 10)]);
            else              shv = fmaxf(acc[o][t], 0.f);
            ov[t] = pv[t] + 0.1f * av[t] + 0.036f * shv;
        }
        *(float4*)&g_P[base] = make_float4(ov[0], ov[1], ov[2], ov[3]);
    }
}

// ---------------------------------------------------------------------------
// K3: causal softmax, one block per row; one float4 per thread. __expf (MUFU).
// ---------------------------------------------------------------------------
__global__ void __launch_bounds__(256) k3_softmax(float* __restrict__ attn_out) {
    const int i = blockIdx.x, n = blockIdx.y;
    const int m = i + 1;
    __shared__ float red[8];
    const int tid = threadIdx.x;
    const int base = (n << 20) + (i << 10);
    const int jb = tid << 2;
    float v0 = -1e30f, v1 = -1e30f, v2 = -1e30f, v3 = -1e30f;
    if (jb < m) {
        float4 pv = *(const float4*)&g_P[base + jb];
        v0 = pv.x;
        v1 = (jb + 1 < m) ? pv.y : -1e30f;
        v2 = (jb + 2 < m) ? pv.z : -1e30f;
        v3 = (jb + 3 < m) ? pv.w : -1e30f;
    }
    float lmax = fmaxf(fmaxf(v0, v1), fmaxf(v2, v3));
#pragma unroll
    for (int o = 16; o > 0; o >>= 1)
        lmax = fmaxf(lmax, __shfl_xor_sync(0xffffffffu, lmax, o));
    if ((tid & 31) == 0) red[tid >> 5] = lmax;
    __syncthreads();
    float mx = red[0];
#pragma unroll
    for (int w = 1; w < 8; w++) mx = fmaxf(mx, red[w]);
    float e0 = (jb     < m) ? __expf(v0 - mx) : 0.f;
    float e1 = (jb + 1 < m) ? __expf(v1 - mx) : 0.f;
    float e2 = (jb + 2 < m) ? __expf(v2 - mx) : 0.f;
    float e3 = (jb + 3 < m) ? __expf(v3 - mx) : 0.f;
    float lsum = (e0 + e1) + (e2 + e3);
#pragma unroll
    for (int o = 16; o > 0; o >>= 1)
        lsum += __shfl_xor_sync(0xffffffffu, lsum, o);
    __syncthreads();
    if ((tid & 31) == 0) red[tid >> 5] = lsum;
    __syncthreads();
    float tot = 0.f;
#pragma unroll
    for (int w = 0; w < 8; w++) tot += red[w];
    const float inv = 1.f / tot;
    *(float4*)&attn_out[base + jb] =
        make_float4(e0 * inv, e1 * inv, e2 * inv, e3 * inv);
}

// ---------------------------------------------------------------------------
// K4: out = attn @ v. 64x64 tile, 4x4 micro, 256 threads (R11 known-good
// config). Heavy blocks (large it => it+1 j-tiles of work) scheduled FIRST
// via it = 15 - blockIdx.x so the long blocks run in wave 1 (LPT order).
// ---------------------------------------------------------------------------
__global__ void __launch_bounds__(256) k4_pv(const float* __restrict__ attn,
                                             const float* __restrict__ v,
                                             float* __restrict__ out) {
    const int it = 15 - blockIdx.x, n = blockIdx.y;
    const int i0 = it << 6;
    __shared__ float sA[64 * 68];   // [j][i]
    __shared__ float sV[64 * 68];   // [j][d]
    const int tid = threadIdx.y * 16 + threadIdx.x;
    const int ty4 = threadIdx.y * 4, tx4 = threadIdx.x * 4;
    float acc[4][4] = {};
    for (int jt = 0; jt <= it; jt++) {
        const int j0 = jt << 6;
        __syncthreads();
        for (int idx = tid; idx < 4096; idx += 256) {
            int rr = idx >> 6, cc = idx & 63;
            sA[cc * 68 + rr] = attn[(n << 20) + ((i0 + rr) << 10) + j0 + cc];
            sV[rr * 68 + cc] = v[(n << 16) + ((j0 + rr) << 6) + cc];
        }
        __syncthreads();
#pragma unroll 8
        for (int lj = 0; lj < 64; lj++) {
            float4 a = *(const float4*)&sA[lj * 68 + ty4];
            float4 b = *(const float4*)&sV[lj * 68 + tx4];
            float av[4] = {a.x, a.y, a.z, a.w};
            float bv[4] = {b.x, b.y, b.z, b.w};
#pragma unroll
            for (int r = 0; r < 4; r++)
#pragma unroll
                for (int c = 0; c < 4; c++)
                    acc[r][c] += av[r] * bv[c];
        }
    }
#pragma unroll
    for (int r = 0; r < 4; r++) {
        const int gi = i0 + ty4 + r;
        *(float4*)&out[(n << 16) + (gi << 6) + tx4] =
            make_float4(acc[r][0], acc[r][1], acc[r][2], acc[r][3]);
    }
}

extern "C" void kernel_launch(void* const* d_in, const int* in_sizes, int n_in,
                              void* d_out, int out_size) {
    const float* q   = (const float*)d_in[0];
    const float* k   = (const float*)d_in[1];
    const float* v   = (const float*)d_in[2];
    const float* qrm = (const float*)d_in[3];
    const float* pre = (const float*)d_in[4];
    const float* cw  = (const float*)d_in[5];
    // d_in[6] = mask (recomputed analytically), d_in[7] = fg (always 1)

    float* out      = (float*)d_out;            // (64,1024,64)
    float* attn_out = out + 64 * 1024 * 64;     // (64,1024,1024)

    const int k1_smem = (3 * 9216 + 2 * 4608) * sizeof(__half);  // 73728 B
    cudaFuncSetAttribute(k1_tc, cudaFuncAttributeMaxDynamicSharedMemorySize,
                         k1_smem);

    k1_tc<<<dim3(16, 8, 64), 256, k1_smem>>>(q, qrm, k);
    k2_conv<<<dim3(32, 32, 8), 256>>>(pre, cw);
    k3_softmax<<<dim3(1024, 64), 256>>>(attn_out);
    k4_pv<<<dim3(16, 64), dim3(16, 16)>>>(attn_out, v, out);
}

// round 15
// speedup vs baseline: 1.1077x; 1.0647x over previous
#include <cuda_runtime.h>
#include <cuda_fp16.h>
#include <cstdint>
#include <math.h>

// Scratch: R = masked q_rm.k/8 stored fp16 (zeros above diagonal; unwritten
// strictly-upper tiles rely on zero-init), P = 0.54*attn + 0.324*attn_rm (f32).
__device__ __half g_R[67108864];
__device__ float  g_P[67108864];

__device__ __forceinline__ void mma16816(float* d,
                                         uint32_t a0, uint32_t a1,
                                         uint32_t a2, uint32_t a3,
                                         uint32_t b0, uint32_t b1) {
    asm volatile(
        "mma.sync.aligned.m16n8k16.row.col.f32.f16.f16.f32 "
        "{%0,%1,%2,%3},{%4,%5,%6,%7},{%8,%9},{%0,%1,%2,%3};\n"
        : "+f"(d[0]), "+f"(d[1]), "+f"(d[2]), "+f"(d[3])
        : "r"(a0), "r"(a1), "r"(a2), "r"(a3), "r"(b0), "r"(b1));
}

// ---------------------------------------------------------------------------
// K1: dual GEMM on tensor cores (P: fp16 split-2, 3 MMAs; R: fp16, 1 MMA).
// C tile 128(i) x 64(j), K=64. Tiles kept iff bx <= 2*by+1.
// ---------------------------------------------------------------------------
__global__ void __launch_bounds__(256) k1_tc(const float* __restrict__ q,
                                             const float* __restrict__ qrm,
                                             const float* __restrict__ kk) {
    const int bx = blockIdx.x, by = blockIdx.y, n = blockIdx.z;
    if (bx > 2 * by + 1) return;
    const int i0 = by << 7, j0 = bx << 6;
    extern __shared__ __half sh[];
    __half* sCh = sh;
    __half* sCl = sh + 9216;
    __half* sRh = sh + 2 * 9216;
    __half* sBh = sh + 3 * 9216;
    __half* sBl = sh + 3 * 9216 + 4608;
    const int tid = threadIdx.x;
    const float* qb = q   + (n << 16) + (i0 << 6);
    const float* rb = qrm + (n << 16) + (i0 << 6);
    const float* kb = kk  + (n << 16) + (j0 << 6);
    for (int p = tid; p < 4096; p += 256) {
        int row = p >> 5, dp = (p & 31) << 1;
        float2 qv = *(const float2*)&qb[(row << 6) + dp];
        float2 rv = *(const float2*)&rb[(row << 6) + dp];
        float c0 = (0.54f * qv.x + 0.324f * rv.x) * 0.125f;
        float c1 = (0.54f * qv.y + 0.324f * rv.y) * 0.125f;
        __half ch0 = __float2half_rn(c0), ch1 = __float2half_rn(c1);
        float l0 = c0 - __half2float(ch0), l1 = c1 - __half2float(ch1);
        int o = row * 72 + dp;
        *(__half2*)&sCh[o] = __halves2half2(ch0, ch1);
        *(__half2*)&sCl[o] = __floats2half2_rn(l0, l1);
        *(__half2*)&sRh[o] = __floats2half2_rn(rv.x * 0.125f, rv.y * 0.125f);
    }
    for (int p = tid; p < 2048; p += 256) {
        int row = p >> 5, dp = (p & 31) << 1;
        float2 kv = *(const float2*)&kb[(row << 6) + dp];
        __half h0 = __float2half_rn(kv.x), h1 = __float2half_rn(kv.y);
        float l0 = kv.x - __half2float(h0), l1 = kv.y - __half2float(h1);
        int o = row * 72 + dp;
        *(__half2*)&sBh[o] = __halves2half2(h0, h1);
        *(__half2*)&sBl[o] = __floats2half2_rn(l0, l1);
    }
    __syncthreads();

    const int w = tid >> 5, lane = tid & 31;
    const int g = lane >> 2, tg = lane & 3;
    const int rowA = 16 * w + g;
    float pA[8][4] = {}, rA[8][4] = {};

#pragma unroll
    for (int kc = 0; kc < 4; kc++) {
        const int kb0 = 16 * kc + 2 * tg;
        const int oa0 = rowA * 72 + kb0;
        const int oa1 = (rowA + 8) * 72 + kb0;
        uint32_t ch0 = *(const uint32_t*)&sCh[oa0];
        uint32_t ch1 = *(const uint32_t*)&sCh[oa1];
        uint32_t ch2 = *(const uint32_t*)&sCh[oa0 + 8];
        uint32_t ch3 = *(const uint32_t*)&sCh[oa1 + 8];
        uint32_t cl0 = *(const uint32_t*)&sCl[oa0];
        uint32_t cl1 = *(const uint32_t*)&sCl[oa1];
        uint32_t cl2 = *(const uint32_t*)&sCl[oa0 + 8];
        uint32_t cl3 = *(const uint32_t*)&sCl[oa1 + 8];
        uint32_t rh0 = *(const uint32_t*)&sRh[oa0];
        uint32_t rh1 = *(const uint32_t*)&sRh[oa1];
        uint32_t rh2 = *(const uint32_t*)&sRh[oa0 + 8];
        uint32_t rh3 = *(const uint32_t*)&sRh[oa1 + 8];
#pragma unroll
        for (int nt = 0; nt < 8; nt++) {
            const int ob = (8 * nt + g) * 72 + kb0;
            uint32_t bh0 = *(const uint32_t*)&sBh[ob];
            uint32_t bh1 = *(const uint32_t*)&sBh[ob + 8];
            uint32_t bl0 = *(const uint32_t*)&sBl[ob];
            uint32_t bl1 = *(const uint32_t*)&sBl[ob + 8];
            mma16816(pA[nt], ch0, ch1, ch2, ch3, bh0, bh1);
            mma16816(pA[nt], ch0, ch1, ch2, ch3, bl0, bl1);
            mma16816(pA[nt], cl0, cl1, cl2, cl3, bh0, bh1);
            mma16816(rA[nt], rh0, rh1, rh2, rh3, bh0, bh1);
        }
    }

    const int r0g = i0 + rowA;
    const int r1g = r0g + 8;
#pragma unroll
    for (int nt = 0; nt < 8; nt++) {
        const int c0 = j0 + 8 * nt + 2 * tg;
        const int off0 = (n << 20) + (r0g << 10) + c0;
        const int off1 = (n << 20) + (r1g << 10) + c0;
        *(float2*)&g_P[off0] = make_float2(pA[nt][0], pA[nt][1]);
        *(float2*)&g_P[off1] = make_float2(pA[nt][2], pA[nt][3]);
        float m00 = (c0     <= r0g) ? rA[nt][0] : 0.f;
        float m01 = (c0 + 1 <= r0g) ? rA[nt][1] : 0.f;
        float m10 = (c0     <= r1g) ? rA[nt][2] : 0.f;
        float m11 = (c0 + 1 <= r1g) ? rA[nt][3] : 0.f;
        *(__half2*)&g_R[off0] = __floats2half2_rn(m00, m01);
        *(__half2*)&g_R[off1] = __floats2half2_rn(m10, m11);
    }
}

// ---------------------------------------------------------------------------
// K2: 3x3 conv on R (fp16), relu, shift, boundary fix, mix into P.
// ---------------------------------------------------------------------------
__global__ void __launch_bounds__(256) k2_conv(const float* __restrict__ pre,
                                               const float* __restrict__ cw) {
    const int bx = blockIdx.x, by = blockIdx.y, b = blockIdx.z;
    if (bx > by) return;
    const int i0 = by << 5, j0 = bx << 5;
    __shared__ float xs[8 * 34 * 34];
    __shared__ float ws[576];
    const int tid = threadIdx.x;
    for (int w = tid; w < 576; w += 256) ws[w] = cw[w];
    for (int idx = tid; idx < 9248; idx += 256) {
        int c = idx / 1156;
        int rem = idx - c * 1156;
        int li = rem / 34;
        int lj = rem - li * 34;
        int gi = i0 - 2 + li, gj = j0 - 2 + lj;
        float vv = 0.f;
        if (gi >= 0 && gj >= 0)
            vv = __half2float(g_R[((b * 8 + c) << 20) + (gi << 10) + gj]);
        xs[idx] = vv;
    }
    __syncthreads();
    const int ir = tid >> 3;
    const int jb = (tid & 7) << 2;
    float acc[8][4];
#pragma unroll
    for (int o = 0; o < 8; o++)
#pragma unroll
        for (int t = 0; t < 4; t++) acc[o][t] = 0.f;
#pragma unroll 1
    for (int c = 0; c < 8; c++) {
#pragma unroll
        for (int kh = 0; kh < 3; kh++) {
            const float* xr = &xs[c * 1156 + (ir + kh) * 34 + jb];
            float x0 = xr[0], x1 = xr[1], x2 = xr[2],
                  x3 = xr[3], x4 = xr[4], x5 = xr[5];
#pragma unroll
            for (int o = 0; o < 8; o++) {
                const float* wp = &ws[o * 72 + c * 9 + kh * 3];
                float w0 = wp[0], w1 = wp[1], w2 = wp[2];
                acc[o][0] += x0 * w0 + x1 * w1 + x2 * w2;
                acc[o][1] += x1 * w0 + x2 * w1 + x3 * w2;
                acc[o][2] += x2 * w0 + x3 * w1 + x4 * w2;
                acc[o][3] += x3 * w0 + x4 * w1 + x5 * w2;
            }
        }
    }
    const int i = i0 + ir;
#pragma unroll
    for (int o = 0; o < 8; o++) {
        const int n = b * 8 + o;
        const int base = (n << 20) + (i << 10) + j0 + jb;
        float4 Pv = *(const float4*)&g_P[base];
        float4 Av = *(const float4*)&pre[base];
        float pv[4] = {Pv.x, Pv.y, Pv.z, Pv.w};
        float av[4] = {Av.x, Av.y, Av.z, Av.w};
        float ov[4];
#pragma unroll
        for (int t = 0; t < 4; t++) {
            const int j = j0 + jb + t;
            float shv;
            if (i == 0)       shv = __half2float(g_R[(n << 20) + j]);
            else if (j == 0)  shv = __half2float(g_R[(n << 20) + (i << 10)]);
            else              shv = fmaxf(acc[o][t], 0.f);
            ov[t] = pv[t] + 0.1f * av[t] + 0.036f * shv;
        }
        *(float4*)&g_P[base] = make_float4(ov[0], ov[1], ov[2], ov[3]);
    }
}

// ---------------------------------------------------------------------------
// K34: fused softmax + PV. Block (it, n) owns rows i0..i0+63.
// Phase 1: warp-per-row causal softmax (8 warps x 8 rows), writes attn
//          probabilities to d_out (required output). No inter-warp reduction.
// Phase 2: R11 k4 PV tile loop; attn reads hit L2 (just written by phase 1).
// ---------------------------------------------------------------------------
__global__ void __launch_bounds__(256) k34_softmax_pv(
        const float* __restrict__ v,
        float* __restrict__ attn_out,
        float* __restrict__ out) {
    const int it = blockIdx.x, n = blockIdx.y;
    const int i0 = it << 6;
    __shared__ float sA[64 * 68];   // [j][i]
    __shared__ float sV[64 * 68];   // [j][d]
    const int tid = threadIdx.y * 16 + threadIdx.x;
    const int w = tid >> 5, lane = tid & 31;

    // ---- Phase 1: softmax of rows i0 + 8w .. i0 + 8w + 7 ----
#pragma unroll 1
    for (int rr = 0; rr < 8; rr++) {
        const int i = i0 + w * 8 + rr;
        const int m = i + 1;
        const int base = (n << 20) + (i << 10);
        float4 vals[8];
        float lmax = -1e30f;
#pragma unroll
        for (int t = 0; t < 8; t++) {
            const int jb = (lane + (t << 5)) << 2;
            float4 pv = make_float4(-1e30f, -1e30f, -1e30f, -1e30f);
            if (jb < m) {
                pv = *(const float4*)&g_P[base + jb];
                if (jb + 1 >= m) pv.y = -1e30f;
                if (jb + 2 >= m) pv.z = -1e30f;
                if (jb + 3 >= m) pv.w = -1e30f;
            }
            vals[t] = pv;
            lmax = fmaxf(lmax, fmaxf(fmaxf(pv.x, pv.y), fmaxf(pv.z, pv.w)));
        }
#pragma unroll
        for (int o = 16; o > 0; o >>= 1)
            lmax = fmaxf(lmax, __shfl_xor_sync(0xffffffffu, lmax, o));
        float lsum = 0.f;
#pragma unroll
        for (int t = 0; t < 8; t++) {
            const int jb = (lane + (t << 5)) << 2;
            float e0 = (jb     < m) ? __expf(vals[t].x - lmax) : 0.f;
            float e1 = (jb + 1 < m) ? __expf(vals[t].y - lmax) : 0.f;
            float e2 = (jb + 2 < m) ? __expf(vals[t].z - lmax) : 0.f;
            float e3 = (jb + 3 < m) ? __expf(vals[t].w - lmax) : 0.f;
            vals[t] = make_float4(e0, e1, e2, e3);
            lsum += (e0 + e1) + (e2 + e3);
        }
#pragma unroll
        for (int o = 16; o > 0; o >>= 1)
            lsum += __shfl_xor_sync(0xffffffffu, lsum, o);
        const float inv = 1.f / lsum;
#pragma unroll
        for (int t = 0; t < 8; t++) {
            const int jb = (lane + (t << 5)) << 2;
            *(float4*)&attn_out[base + jb] =
                make_float4(vals[t].x * inv, vals[t].y * inv,
                            vals[t].z * inv, vals[t].w * inv);
        }
    }
    __syncthreads();

    // ---- Phase 2: out = attn @ v (R11 k4 structure, attn L2-hot) ----
    const int ty4 = threadIdx.y * 4, tx4 = threadIdx.x * 4;
    float acc[4][4] = {};
    for (int jt = 0; jt <= it; jt++) {
        const int j0 = jt << 6;
        __syncthreads();
        for (int idx = tid; idx < 4096; idx += 256) {
            int rr = idx >> 6, cc = idx & 63;
            sA[cc * 68 + rr] = attn_out[(n << 20) + ((i0 + rr) << 10) + j0 + cc];
            sV[rr * 68 + cc] = v[(n << 16) + ((j0 + rr) << 6) + cc];
        }
        __syncthreads();
#pragma unroll 8
        for (int lj = 0; lj < 64; lj++) {
            float4 a = *(const float4*)&sA[lj * 68 + ty4];
            float4 b = *(const float4*)&sV[lj * 68 + tx4];
            float av[4] = {a.x, a.y, a.z, a.w};
            float bv[4] = {b.x, b.y, b.z, b.w};
#pragma unroll
            for (int r = 0; r < 4; r++)
#pragma unroll
                for (int c = 0; c < 4; c++)
                    acc[r][c] += av[r] * bv[c];
        }
    }
#pragma unroll
    for (int r = 0; r < 4; r++) {
        const int gi = i0 + ty4 + r;
        *(float4*)&out[(n << 16) + (gi << 6) + tx4] =
            make_float4(acc[r][0], acc[r][1], acc[r][2], acc[r][3]);
    }
}

extern "C" void kernel_launch(void* const* d_in, const int* in_sizes, int n_in,
                              void* d_out, int out_size) {
    const float* q   = (const float*)d_in[0];
    const float* k   = (const float*)d_in[1];
    const float* v   = (const float*)d_in[2];
    const float* qrm = (const float*)d_in[3];
    const float* pre = (const float*)d_in[4];
    const float* cw  = (const float*)d_in[5];
    // d_in[6] = mask (recomputed analytically), d_in[7] = fg (always 1)

    float* out      = (float*)d_out;            // (64,1024,64)
    float* attn_out = out + 64 * 1024 * 64;     // (64,1024,1024)

    const int k1_smem = (3 * 9216 + 2 * 4608) * sizeof(__half);  // 73728 B
    cudaFuncSetAttribute(k1_tc, cudaFuncAttributeMaxDynamicSharedMemorySize,
                         k1_smem);

    k1_tc<<<dim3(16, 8, 64), 256, k1_smem>>>(q, qrm, k);
    k2_conv<<<dim3(32, 32, 8), 256>>>(pre, cw);
    k34_softmax_pv<<<dim3(16, 64), dim3(16, 16)>>>(v, attn_out, out);
}